// round 8
// baseline (speedup 1.0000x reference)
#include <cuda_runtime.h>
#include <cuda_fp16.h>
#include <cstdint>
#include <cstddef>
#include <cmath>

// Problem constants
#define T_STEPS 1000
#define BATCH   64
#define NDIM    512
#define KDIM    512
#define MROWS   (BATCH * T_STEPS)   // 64000

static constexpr size_t PLANE      = (size_t)BATCH * NDIM;          // 32768
static constexpr size_t STATES_OFF = (size_t)T_STEPS * PLANE;       // outputs plane elems
static constexpr size_t DEC_OFF    = STATES_OFF + 3 * STATES_OFF;   // after states [T,3,B,N]

// Scratch
__device__ __align__(16) float    g_I[(size_t)MROWS * NDIM];
__device__ __align__(16) uint32_t g_Xp[(size_t)MROWS * KDIM];   // packed hi/lo X
__device__ __align__(16) uint32_t g_Wp[(size_t)NDIM * KDIM];    // packed hi/lo W1
__device__ float g_r[T_STEPS * BATCH];

// ---------------------------------------------------------------------------
// fp16 Dekker-pair: x -> half2(hi=rn16(x), lo=rn16(x-hi)). Interleaved along
// mma-k: pass1 (A x B) = hi*hi + lo*lo; pass2 (A x swap16(B)) = hi*lo + lo*hi.
// Sum = full (hi+lo)(hi+lo) product, ~2^-22 relative error.
// ---------------------------------------------------------------------------
__device__ __forceinline__ uint32_t pack_hilo(float x) {
    __half h = __float2half_rn(x);
    float r = x - __half2float(h);
    __half2 p = __halves2half2(h, __float2half_rn(r));
    return *reinterpret_cast<uint32_t*>(&p);
}

__device__ __forceinline__ void mma_f16(float* c, const uint32_t* a, const uint32_t* b) {
    asm volatile(
        "mma.sync.aligned.m16n8k16.row.col.f32.f16.f16.f32 "
        "{%0,%1,%2,%3}, {%4,%5,%6,%7}, {%8,%9}, {%0,%1,%2,%3};\n"
        : "+f"(c[0]), "+f"(c[1]), "+f"(c[2]), "+f"(c[3])
        : "r"(a[0]), "r"(a[1]), "r"(a[2]), "r"(a[3]), "r"(b[0]), "r"(b[1]));
}

__device__ __forceinline__ void cp_async16(uint32_t smem_dst, const void* gptr) {
    asm volatile("cp.async.cg.shared.global [%0], [%1], 16;"
                 :: "r"(smem_dst), "l"(gptr) : "memory");
}
#define CP_COMMIT() asm volatile("cp.async.commit_group;" ::: "memory")
#define CP_WAIT(N)  asm volatile("cp.async.wait_group %0;" :: "n"(N) : "memory")

// ---------------------------------------------------------------------------
// Kernel 0: pack f32 -> hi/lo half2 words (one pass, memory-bound)
// ---------------------------------------------------------------------------
__global__ __launch_bounds__(256) void pack_kernel(const float* __restrict__ src,
                                                   uint32_t* __restrict__ dst, int n4)
{
    const int i = blockIdx.x * 256 + threadIdx.x;
    if (i < n4) {
        float4 v = ((const float4*)src)[i];
        uint4 w;
        w.x = pack_hilo(v.x); w.y = pack_hilo(v.y);
        w.z = pack_hilo(v.z); w.w = pack_hilo(v.w);
        ((uint4*)dst)[i] = w;
    }
}

// ---------------------------------------------------------------------------
// Kernel 1: I = X @ W1^T (NT GEMM) on pre-packed operands.
// Mainloop = cp.async + LDS + mma only. 512 threads, 16 warps 4x4, warp tile
// 32x32, 4-stage pipeline, stride-36-word smem rows (conflict-free LDS).
// Tile = 128*36 words = 18KB; stage (A+B) = 36KB; 4 stages = 144KB.
// ---------------------------------------------------------------------------
#define BKR    32                  // real-k words per chunk
#define NCHUNK (KDIM / BKR)        // 16
#define WSTR   36                  // words per smem row (32 data + 4 pad)
#define TILEW  (128 * WSTR)
#define STAGEW (2 * TILEW)

__device__ __forceinline__ void issue_chunk(uint32_t smem_base_u32, int stage,
                                            const uint32_t* __restrict__ xp,
                                            const uint32_t* __restrict__ wp,
                                            int ck, int lrow, int lkb)
{
    // per thread: 8 words of A (2x16B) + 8 words of B (2x16B)
    const uint32_t dA = smem_base_u32 +
        (uint32_t)(stage * STAGEW + lrow * WSTR + lkb) * 4u;
    const uint32_t dB = dA + (uint32_t)TILEW * 4u;
    const uint32_t* xs = xp + ck * BKR;
    const uint32_t* ws = wp + ck * BKR;
    cp_async16(dA,      xs);
    cp_async16(dA + 16, xs + 4);
    cp_async16(dB,      ws);
    cp_async16(dB + 16, ws + 4);
}

__device__ __forceinline__ void compute_chunk(const uint32_t* __restrict__ stage,
                                              float (&acc)[2][4][4],
                                              int wm, int wn, int lane)
{
    const uint32_t* sA = stage;
    const uint32_t* sB = stage + TILEW;
    const int lq = lane >> 2;        // 0..7
    const int lr = lane & 3;         // 0..3

    #pragma unroll
    for (int s = 0; s < 4; s++) {
        const int c0 = s * 8 + lr;
        uint32_t A[2][4];
        #pragma unroll
        for (int mt = 0; mt < 2; mt++) {
            const int r0 = wm * 32 + mt * 16 + lq;
            A[mt][0] = sA[r0 * WSTR + c0];
            A[mt][1] = sA[(r0 + 8) * WSTR + c0];
            A[mt][2] = sA[r0 * WSTR + c0 + 4];
            A[mt][3] = sA[(r0 + 8) * WSTR + c0 + 4];
        }
        uint32_t B[4][2];
        #pragma unroll
        for (int nt = 0; nt < 4; nt++) {
            const int nr = wn * 32 + nt * 8 + lq;
            B[nt][0] = sB[nr * WSTR + c0];
            B[nt][1] = sB[nr * WSTR + c0 + 4];
        }
        // pass 1: hi*hi + lo*lo — distinct accumulators
        #pragma unroll
        for (int mt = 0; mt < 2; mt++)
            #pragma unroll
            for (int nt = 0; nt < 4; nt++)
                mma_f16(acc[mt][nt], A[mt], B[nt]);
        // pass 2: hi*lo + lo*hi — swapped-half B
        #pragma unroll
        for (int nt = 0; nt < 4; nt++) {
            uint32_t bs[2];
            bs[0] = __byte_perm(B[nt][0], 0, 0x1032);
            bs[1] = __byte_perm(B[nt][1], 0, 0x1032);
            #pragma unroll
            for (int mt = 0; mt < 2; mt++)
                mma_f16(acc[mt][nt], A[mt], bs);
        }
    }
}

__global__ __launch_bounds__(512, 1) void gemm_f16pair_kernel()
{
    extern __shared__ uint32_t smemw[];      // 4 stages * 9216 words = 144KB
    const int tid  = threadIdx.x;
    const int wid  = tid >> 5;
    const int lane = tid & 31;
    const int wm   = wid & 3;                // 0..3 (M)
    const int wn   = wid >> 2;               // 0..3 (N)
    const int bm   = blockIdx.x * 128;
    const int bn   = blockIdx.y * 128;

    const uint32_t smem_u = (uint32_t)__cvta_generic_to_shared(smemw);

    // loader mapping: row = tid>>2 (0..127), kb = (tid&3)*8 words
    const int lrow = tid >> 2;
    const int lkb  = (tid & 3) * 8;
    const uint32_t* xp = g_Xp + (size_t)(bm + lrow) * KDIM + lkb;
    const uint32_t* wp = g_Wp + (size_t)(bn + lrow) * KDIM + lkb;

    float acc[2][4][4];
    #pragma unroll
    for (int mt = 0; mt < 2; mt++)
        #pragma unroll
        for (int nt = 0; nt < 4; nt++)
            #pragma unroll
            for (int j = 0; j < 4; j++) acc[mt][nt][j] = 0.f;

    // Prologue: fill 3 stages
    #pragma unroll
    for (int s = 0; s < 3; s++) {
        issue_chunk(smem_u, s, xp, wp, s, lrow, lkb);
        CP_COMMIT();
    }

    #pragma unroll 1
    for (int ck = 0; ck < NCHUNK; ck++) {
        CP_WAIT(2);                  // chunk ck's group landed
        __syncthreads();             // stage (ck+3)&3 free (compute ck-1 done by all)
        if (ck + 3 < NCHUNK) {
            issue_chunk(smem_u, (ck + 3) & 3, xp, wp, ck + 3, lrow, lkb);
            CP_COMMIT();
        } else {
            CP_COMMIT();             // keep group count uniform for CP_WAIT(2)
        }
        compute_chunk(smemw + (ck & 3) * STAGEW, acc, wm, wn, lane);
    }

    // Epilogue: direct float2 stores to g_I
    #pragma unroll
    for (int mt = 0; mt < 2; mt++) {
        const int r0 = bm + wm * 32 + mt * 16 + (lane >> 2);
        #pragma unroll
        for (int nt = 0; nt < 4; nt++) {
            const int c = bn + wn * 32 + nt * 8 + 2 * (lane & 3);
            *(float2*)(g_I + (size_t)r0 * NDIM + c)       = make_float2(acc[mt][nt][0], acc[mt][nt][1]);
            *(float2*)(g_I + (size_t)(r0 + 8) * NDIM + c) = make_float2(acc[mt][nt][2], acc[mt][nt][3]);
        }
    }
}

// ---------------------------------------------------------------------------
// Kernel 2: per-neuron Izhikevich scan (frozen)
// ---------------------------------------------------------------------------
struct NeuronP { float TS, V2, V1, V0, KA, Bp, TH, Cc, D; };

__device__ __forceinline__ void snn_step(float Ic, int t, int g,
                                         const NeuronP& P, float& u, float& v,
                                         float* __restrict__ out)
{
    float t0 = P.V0 - u + Ic;
    t0 = fmaf(P.V1, v, t0);
    t0 = fmaf(P.V2, v * v, t0);
    const float vn = fmaf(P.TS, t0, v);
    const float un = fmaf(P.KA, fmaf(P.Bp, v, -u), u);
    const bool  sp = (vn - P.TH) > 0.f;
    const float s  = sp ? 1.f : 0.f;
    const float vo = sp ? P.Cc : vn;
    const float uo = sp ? (un + P.D) : un;

    out[(size_t)t * PLANE + g] = s;
    const size_t sb = STATES_OFF + (size_t)t * (3 * PLANE) + g;
    out[sb]             = uo;
    out[sb + PLANE]     = vo;
    out[sb + 2 * PLANE] = s;
    u = uo; v = vo;
}

__global__ __launch_bounds__(128) void scan_kernel(
    const float* __restrict__ st,
    const float* __restrict__ pa,  const float* __restrict__ pb,
    const float* __restrict__ pc,  const float* __restrict__ pd,
    const float* __restrict__ pv2, const float* __restrict__ pv1,
    const float* __restrict__ pv0, const float* __restrict__ ptau,
    const float* __restrict__ pth, const float* __restrict__ pts,
    float* __restrict__ out)
{
    const int g = blockIdx.x * 128 + threadIdx.x;
    const int n = g & (NDIM - 1);

    NeuronP P;
    P.TS = pts[n];
    P.V2 = pv2[n]; P.V1 = pv1[n]; P.V0 = pv0[n];
    P.KA = P.TS / ptau[n] * pa[n];
    P.Bp = pb[n]; P.TH = pth[n]; P.Cc = pc[n]; P.D = pd[n];

    float u = st[g];
    float v = st[PLANE + g];

    const float* Ip = g_I + (size_t)(g >> 9) * ((size_t)T_STEPS * NDIM) + n;

    float bufA[8], bufB[8];
    #pragma unroll
    for (int p = 0; p < 8; p++) bufA[p] = Ip[(size_t)p * NDIM];

    #pragma unroll 1
    for (int t0 = 0; t0 < 992; t0 += 16) {
        #pragma unroll
        for (int p = 0; p < 8; p++) bufB[p] = Ip[(size_t)(t0 + 8 + p) * NDIM];
        #pragma unroll
        for (int p = 0; p < 8; p++) snn_step(bufA[p], t0 + p, g, P, u, v, out);
        #pragma unroll
        for (int p = 0; p < 8; p++) bufA[p] = Ip[(size_t)(t0 + 16 + p) * NDIM];
        #pragma unroll
        for (int p = 0; p < 8; p++) snn_step(bufB[p], t0 + 8 + p, g, P, u, v, out);
    }
    #pragma unroll
    for (int p = 0; p < 8; p++) snn_step(bufA[p], 992 + p, g, P, u, v, out);
}

// ---------------------------------------------------------------------------
// Kernel 3: r[t*B+b] = sum_n s[t,b,n] * W2[n]  (frozen)
// ---------------------------------------------------------------------------
__global__ __launch_bounds__(128) void readout_reduce_kernel(
    const float* __restrict__ out, const float* __restrict__ W2)
{
    const int tb = blockIdx.x;
    const float* sp = out + (size_t)tb * NDIM;
    const int tid = threadIdx.x;

    float sum = 0.f;
    #pragma unroll
    for (int j = 0; j < 4; j++) {
        const int n = tid + j * 128;
        sum = fmaf(sp[n], W2[n], sum);
    }
    #pragma unroll
    for (int o = 16; o > 0; o >>= 1)
        sum += __shfl_xor_sync(0xffffffffu, sum, o);

    __shared__ float ws[4];
    if ((tid & 31) == 0) ws[tid >> 5] = sum;
    __syncthreads();
    if (tid == 0) g_r[tb] = (ws[0] + ws[1]) + (ws[2] + ws[3]);
}

// ---------------------------------------------------------------------------
// Kernel 4: li recurrence — warp-parallel linear-recurrence scan (frozen)
// ---------------------------------------------------------------------------
__global__ void li_kernel(const float* __restrict__ stLI,
                          const float* __restrict__ leak,
                          float* __restrict__ out)
{
    const int b = blockIdx.x;
    const int lane = threadIdx.x;    // 32 threads
    const float lk = leak[0];
    const float l1 = lk, l2 = l1 * l1, l4 = l2 * l2, l8 = l4 * l4, l16 = l8 * l8;
    float lpow = lk;                 // leak^(lane+1)
    {
        float sq[5] = {l1, l2, l4, l8, l16};
        #pragma unroll
        for (int i = 0; i < 5; i++)
            if ((lane >> i) & 1) lpow *= sq[i];
    }

    float carry = stLI[b];
    float x = g_r[lane * BATCH + b];

    #pragma unroll 1
    for (int t0 = 0; t0 < T_STEPS; t0 += 32) {
        const int tn = t0 + 32 + lane;
        const float xn = (tn < T_STEPS) ? g_r[tn * BATCH + b] : 0.f;

        float y = x, up;
        up = __shfl_up_sync(0xffffffffu, y, 1);  if (lane >= 1)  y = fmaf(l1,  up, y);
        up = __shfl_up_sync(0xffffffffu, y, 2);  if (lane >= 2)  y = fmaf(l2,  up, y);
        up = __shfl_up_sync(0xffffffffu, y, 4);  if (lane >= 4)  y = fmaf(l4,  up, y);
        up = __shfl_up_sync(0xffffffffu, y, 8);  if (lane >= 8)  y = fmaf(l8,  up, y);
        up = __shfl_up_sync(0xffffffffu, y, 16); if (lane >= 16) y = fmaf(l16, up, y);

        const float li = fmaf(lpow, carry, y);
        if (t0 + lane < T_STEPS)
            out[DEC_OFF + (size_t)(t0 + lane) * BATCH + b] = li;
        carry = __shfl_sync(0xffffffffu, li, 31);
        x = xn;
    }
}

// ---------------------------------------------------------------------------
extern "C" void kernel_launch(void* const* d_in, const int* in_sizes, int n_in,
                              void* d_out, int out_size)
{
    const float* x    = (const float*)d_in[0];
    const float* st   = (const float*)d_in[1];
    const float* stLI = (const float*)d_in[2];
    const float* W1   = (const float*)d_in[3];
    const float* W2   = (const float*)d_in[4];
    const float* a_   = (const float*)d_in[5];
    const float* b_   = (const float*)d_in[6];
    const float* c_   = (const float*)d_in[7];
    const float* d_   = (const float*)d_in[8];
    const float* v2_  = (const float*)d_in[9];
    const float* v1_  = (const float*)d_in[10];
    const float* v0_  = (const float*)d_in[11];
    const float* tau_ = (const float*)d_in[12];
    const float* th_  = (const float*)d_in[13];
    const float* lk_  = (const float*)d_in[14];
    const float* ts_  = (const float*)d_in[15];
    float* out = (float*)d_out;

    // Resolve device-global addresses (host-side, graph-capture safe)
    uint32_t* xp_addr = nullptr;
    uint32_t* wp_addr = nullptr;
    cudaGetSymbolAddress((void**)&xp_addr, g_Xp);
    cudaGetSymbolAddress((void**)&wp_addr, g_Wp);

    const int smem_bytes = 4 * STAGEW * (int)sizeof(uint32_t);   // 147456
    cudaFuncSetAttribute(gemm_f16pair_kernel,
                         cudaFuncAttributeMaxDynamicSharedMemorySize, smem_bytes);

    // Kernel 0: pack X and W1 into hi/lo half2 words
    pack_kernel<<<(MROWS * KDIM / 4 + 255) / 256, 256>>>(x,  xp_addr, MROWS * KDIM / 4);
    pack_kernel<<<(NDIM * KDIM / 4 + 255) / 256, 256>>>(W1, wp_addr, NDIM * KDIM / 4);

    dim3 ggrid(MROWS / 128, NDIM / 128);   // (500, 4)
    gemm_f16pair_kernel<<<ggrid, 512, smem_bytes>>>();
    scan_kernel<<<(BATCH * NDIM) / 128, 128>>>(st, a_, b_, c_, d_, v2_, v1_,
                                               v0_, tau_, th_, ts_, out);
    readout_reduce_kernel<<<T_STEPS * BATCH, 128>>>(out, W2);
    li_kernel<<<BATCH, 32>>>(stLI, lk_, out);
}

// round 9
// speedup vs baseline: 1.1230x; 1.1230x over previous
#include <cuda_runtime.h>
#include <cuda_fp16.h>
#include <cstdint>
#include <cstddef>
#include <cmath>

// Problem constants
#define T_STEPS 1000
#define BATCH   64
#define NDIM    512
#define KDIM    512
#define MROWS   (BATCH * T_STEPS)   // 64000

static constexpr size_t PLANE      = (size_t)BATCH * NDIM;          // 32768
static constexpr size_t STATES_OFF = (size_t)T_STEPS * PLANE;       // outputs plane elems
static constexpr size_t DEC_OFF    = STATES_OFF + 3 * STATES_OFF;   // after states [T,3,B,N]

// Scratch
__device__ __align__(16) float g_I[(size_t)MROWS * NDIM];
__device__ float g_r[T_STEPS * BATCH];

// ---------------------------------------------------------------------------
// fp16 Dekker-pair: x -> half2(hi=rn16(x), lo=rn16(x-hi)), interleaved along
// mma-k. pass1 (A x B) = hi*hi + lo*lo; pass2 (A x swap16(B)) = hi*lo + lo*hi.
// Sum = full (hi+lo)(hi+lo) product, ~2^-22 relative error.
// ---------------------------------------------------------------------------
__device__ __forceinline__ uint32_t pack_hilo(float x) {
    __half h = __float2half_rn(x);
    float r = x - __half2float(h);
    __half2 p = __halves2half2(h, __float2half_rn(r));
    return *reinterpret_cast<uint32_t*>(&p);
}

__device__ __forceinline__ void mma_f16(float* c, const uint32_t* a, const uint32_t* b) {
    asm volatile(
        "mma.sync.aligned.m16n8k16.row.col.f32.f16.f16.f32 "
        "{%0,%1,%2,%3}, {%4,%5,%6,%7}, {%8,%9}, {%0,%1,%2,%3};\n"
        : "+f"(c[0]), "+f"(c[1]), "+f"(c[2]), "+f"(c[3])
        : "r"(a[0]), "r"(a[1]), "r"(a[2]), "r"(a[3]), "r"(b[0]), "r"(b[1]));
}

__device__ __forceinline__ void ldsm_x4(uint32_t* r, uint32_t saddr) {
    asm volatile("ldmatrix.sync.aligned.m8n8.x4.shared.b16 {%0,%1,%2,%3}, [%4];"
                 : "=r"(r[0]), "=r"(r[1]), "=r"(r[2]), "=r"(r[3]) : "r"(saddr));
}

// ---------------------------------------------------------------------------
// Kernel 1: I = X @ W1^T (NT GEMM), fp16 Dekker-pair mma, 2 passes.
// R7 skeleton (512 threads, 16 warps 4x4, warp tile 32x32, register-staged
// double buffer, stride-36-word smem) with ldmatrix fragment loads:
//   A m16k16 fragment  = one ldmatrix.x4 (was 8 LDS.32)
//   B n16k16 (2 nt)    = one ldmatrix.x4 (was 16 LDS.32)
// 16 LDSM vs 64 LDS per warp-chunk. Conflict-free: row stride 36 words.
// ---------------------------------------------------------------------------
#define BKR    32
#define NCHUNK (KDIM / BKR)        // 16
#define WSTR   36                  // uint32 words per row (32 data + 4 pad)
#define TILEW  (128 * WSTR)
#define STAGEW (2 * TILEW)

struct LdgRegs { float4 a[2]; float4 b[2]; };

__device__ __forceinline__ void ldg_chunk(LdgRegs& r, const float* __restrict__ xptr,
                                          const float* __restrict__ wptr, int ck)
{
    const float4* xa = (const float4*)(xptr + ck * BKR);
    const float4* wa = (const float4*)(wptr + ck * BKR);
    r.a[0] = xa[0]; r.a[1] = xa[1];
    r.b[0] = wa[0]; r.b[1] = wa[1];
}

__device__ __forceinline__ void sts_chunk(uint32_t* stage, const LdgRegs& r, int row, int kb)
{
    uint32_t* sA = stage + row * WSTR + kb;
    uint32_t* sB = sA + TILEW;
    const float* fa = (const float*)r.a;
    const float* fb = (const float*)r.b;
    #pragma unroll
    for (int j = 0; j < 2; j++) {
        uint4 w;
        w.x = pack_hilo(fa[j * 4 + 0]); w.y = pack_hilo(fa[j * 4 + 1]);
        w.z = pack_hilo(fa[j * 4 + 2]); w.w = pack_hilo(fa[j * 4 + 3]);
        ((uint4*)sA)[j] = w;
    }
    #pragma unroll
    for (int j = 0; j < 2; j++) {
        uint4 w;
        w.x = pack_hilo(fb[j * 4 + 0]); w.y = pack_hilo(fb[j * 4 + 1]);
        w.z = pack_hilo(fb[j * 4 + 2]); w.w = pack_hilo(fb[j * 4 + 3]);
        ((uint4*)sB)[j] = w;
    }
}

// aBase/bBase: per-lane smem byte addresses (stage-relative) for ldmatrix.
__device__ __forceinline__ void compute_chunk(uint32_t stage_saddr,
                                              float (&acc)[2][4][4],
                                              uint32_t aOff, uint32_t bOff)
{
    #pragma unroll
    for (int s = 0; s < 4; s++) {
        const uint32_t kByte = (uint32_t)(s * 8) * 4u;
        uint32_t A[2][4];
        ldsm_x4(A[0], stage_saddr + aOff + kByte);                       // mt=0
        ldsm_x4(A[1], stage_saddr + aOff + (uint32_t)(16 * WSTR * 4) + kByte); // mt=1
        uint32_t Bt[2][4];
        ldsm_x4(Bt[0], stage_saddr + bOff + kByte);                      // nt 0,1
        ldsm_x4(Bt[1], stage_saddr + bOff + (uint32_t)(16 * WSTR * 4) + kByte); // nt 2,3
        // Bt[p] = {nt(2p).b0, nt(2p).b1, nt(2p+1).b0, nt(2p+1).b1}

        // pass 1: hi*hi + lo*lo — distinct accumulators
        #pragma unroll
        for (int mt = 0; mt < 2; mt++)
            #pragma unroll
            for (int nt = 0; nt < 4; nt++)
                mma_f16(acc[mt][nt], A[mt], &Bt[nt >> 1][(nt & 1) * 2]);
        // pass 2: hi*lo + lo*hi — swapped-half B
        #pragma unroll
        for (int nt = 0; nt < 4; nt++) {
            uint32_t bs[2];
            bs[0] = __byte_perm(Bt[nt >> 1][(nt & 1) * 2 + 0], 0, 0x1032);
            bs[1] = __byte_perm(Bt[nt >> 1][(nt & 1) * 2 + 1], 0, 0x1032);
            #pragma unroll
            for (int mt = 0; mt < 2; mt++)
                mma_f16(acc[mt][nt], A[mt], bs);
        }
    }
}

__global__ __launch_bounds__(512, 1) void gemm_f16pair_kernel(const float* __restrict__ X,
                                                              const float* __restrict__ W)
{
    extern __shared__ uint32_t smemw[];      // 2 stages * 9216 words = 72KB
    const int tid  = threadIdx.x;
    const int wid  = tid >> 5;
    const int lane = tid & 31;
    const int wm   = wid & 3;                // 0..3 (M)
    const int wn   = wid >> 2;               // 0..3 (N)
    const int bm   = blockIdx.x * 128;
    const int bn   = blockIdx.y * 128;

    const uint32_t smem_saddr = (uint32_t)__cvta_generic_to_shared(smemw);

    // ldmatrix per-lane offsets (stage-relative, bytes).
    // A x4: M0=rows+0/w0, M1=rows+8/w0, M2=rows+0/w4, M3=rows+8/w4
    const int lm = lane & 7;
    const int aRow = wm * 32 + lm + ((lane >> 3) & 1) * 8;
    const int aWrd = ((lane >> 4) & 1) * 4;
    const uint32_t aOff = (uint32_t)(aRow * WSTR + aWrd) * 4u;
    // B x4: M0=rows+0/w0, M1=rows+0/w4, M2=rows+8/w0, M3=rows+8/w4
    const int bRow = wn * 32 + lm + ((lane >> 4) & 1) * 8;
    const int bWrd = ((lane >> 3) & 1) * 4;
    const uint32_t bOff = (uint32_t)(TILEW + bRow * WSTR + bWrd) * 4u;

    // loader mapping: row = tid>>2 (0..127), kb = (tid&3)*8 words
    const int lrow = tid >> 2;
    const int lkb  = (tid & 3) * 8;
    const float* xptr = X + (size_t)(bm + lrow) * KDIM + lkb;
    const float* wptr = W + (size_t)(bn + lrow) * KDIM + lkb;

    float acc[2][4][4];
    #pragma unroll
    for (int mt = 0; mt < 2; mt++)
        #pragma unroll
        for (int nt = 0; nt < 4; nt++)
            #pragma unroll
            for (int j = 0; j < 4; j++) acc[mt][nt][j] = 0.f;

    {
        LdgRegs r0;
        ldg_chunk(r0, xptr, wptr, 0);
        sts_chunk(smemw, r0, lrow, lkb);
    }
    __syncthreads();

    #pragma unroll 1
    for (int ck = 0; ck < NCHUNK; ck++) {
        const int cur = ck & 1;
        LdgRegs nr;
        if (ck < NCHUNK - 1) ldg_chunk(nr, xptr, wptr, ck + 1);   // LDGs in flight
        compute_chunk(smem_saddr + (uint32_t)(cur * STAGEW) * 4u, acc, aOff, bOff);
        if (ck < NCHUNK - 1) sts_chunk(smemw + (cur ^ 1) * STAGEW, nr, lrow, lkb);
        __syncthreads();
    }

    // Epilogue: direct float2 stores to g_I
    #pragma unroll
    for (int mt = 0; mt < 2; mt++) {
        const int r0 = bm + wm * 32 + mt * 16 + (lane >> 2);
        #pragma unroll
        for (int nt = 0; nt < 4; nt++) {
            const int c = bn + wn * 32 + nt * 8 + 2 * (lane & 3);
            *(float2*)(g_I + (size_t)r0 * NDIM + c)       = make_float2(acc[mt][nt][0], acc[mt][nt][1]);
            *(float2*)(g_I + (size_t)(r0 + 8) * NDIM + c) = make_float2(acc[mt][nt][2], acc[mt][nt][3]);
        }
    }
}

// ---------------------------------------------------------------------------
// Kernel 2: per-neuron Izhikevich scan (frozen)
// ---------------------------------------------------------------------------
struct NeuronP { float TS, V2, V1, V0, KA, Bp, TH, Cc, D; };

__device__ __forceinline__ void snn_step(float Ic, int t, int g,
                                         const NeuronP& P, float& u, float& v,
                                         float* __restrict__ out)
{
    float t0 = P.V0 - u + Ic;
    t0 = fmaf(P.V1, v, t0);
    t0 = fmaf(P.V2, v * v, t0);
    const float vn = fmaf(P.TS, t0, v);
    const float un = fmaf(P.KA, fmaf(P.Bp, v, -u), u);
    const bool  sp = (vn - P.TH) > 0.f;
    const float s  = sp ? 1.f : 0.f;
    const float vo = sp ? P.Cc : vn;
    const float uo = sp ? (un + P.D) : un;

    out[(size_t)t * PLANE + g] = s;
    const size_t sb = STATES_OFF + (size_t)t * (3 * PLANE) + g;
    out[sb]             = uo;
    out[sb + PLANE]     = vo;
    out[sb + 2 * PLANE] = s;
    u = uo; v = vo;
}

__global__ __launch_bounds__(128) void scan_kernel(
    const float* __restrict__ st,
    const float* __restrict__ pa,  const float* __restrict__ pb,
    const float* __restrict__ pc,  const float* __restrict__ pd,
    const float* __restrict__ pv2, const float* __restrict__ pv1,
    const float* __restrict__ pv0, const float* __restrict__ ptau,
    const float* __restrict__ pth, const float* __restrict__ pts,
    float* __restrict__ out)
{
    const int g = blockIdx.x * 128 + threadIdx.x;
    const int n = g & (NDIM - 1);

    NeuronP P;
    P.TS = pts[n];
    P.V2 = pv2[n]; P.V1 = pv1[n]; P.V0 = pv0[n];
    P.KA = P.TS / ptau[n] * pa[n];
    P.Bp = pb[n]; P.TH = pth[n]; P.Cc = pc[n]; P.D = pd[n];

    float u = st[g];
    float v = st[PLANE + g];

    const float* Ip = g_I + (size_t)(g >> 9) * ((size_t)T_STEPS * NDIM) + n;

    float bufA[8], bufB[8];
    #pragma unroll
    for (int p = 0; p < 8; p++) bufA[p] = Ip[(size_t)p * NDIM];

    #pragma unroll 1
    for (int t0 = 0; t0 < 992; t0 += 16) {
        #pragma unroll
        for (int p = 0; p < 8; p++) bufB[p] = Ip[(size_t)(t0 + 8 + p) * NDIM];
        #pragma unroll
        for (int p = 0; p < 8; p++) snn_step(bufA[p], t0 + p, g, P, u, v, out);
        #pragma unroll
        for (int p = 0; p < 8; p++) bufA[p] = Ip[(size_t)(t0 + 16 + p) * NDIM];
        #pragma unroll
        for (int p = 0; p < 8; p++) snn_step(bufB[p], t0 + 8 + p, g, P, u, v, out);
    }
    #pragma unroll
    for (int p = 0; p < 8; p++) snn_step(bufA[p], 992 + p, g, P, u, v, out);
}

// ---------------------------------------------------------------------------
// Kernel 3: r[t*B+b] = sum_n s[t,b,n] * W2[n]  (frozen)
// ---------------------------------------------------------------------------
__global__ __launch_bounds__(128) void readout_reduce_kernel(
    const float* __restrict__ out, const float* __restrict__ W2)
{
    const int tb = blockIdx.x;
    const float* sp = out + (size_t)tb * NDIM;
    const int tid = threadIdx.x;

    float sum = 0.f;
    #pragma unroll
    for (int j = 0; j < 4; j++) {
        const int n = tid + j * 128;
        sum = fmaf(sp[n], W2[n], sum);
    }
    #pragma unroll
    for (int o = 16; o > 0; o >>= 1)
        sum += __shfl_xor_sync(0xffffffffu, sum, o);

    __shared__ float ws[4];
    if ((tid & 31) == 0) ws[tid >> 5] = sum;
    __syncthreads();
    if (tid == 0) g_r[tb] = (ws[0] + ws[1]) + (ws[2] + ws[3]);
}

// ---------------------------------------------------------------------------
// Kernel 4: li recurrence — warp-parallel linear-recurrence scan (frozen)
// ---------------------------------------------------------------------------
__global__ void li_kernel(const float* __restrict__ stLI,
                          const float* __restrict__ leak,
                          float* __restrict__ out)
{
    const int b = blockIdx.x;
    const int lane = threadIdx.x;    // 32 threads
    const float lk = leak[0];
    const float l1 = lk, l2 = l1 * l1, l4 = l2 * l2, l8 = l4 * l4, l16 = l8 * l8;
    float lpow = lk;                 // leak^(lane+1)
    {
        float sq[5] = {l1, l2, l4, l8, l16};
        #pragma unroll
        for (int i = 0; i < 5; i++)
            if ((lane >> i) & 1) lpow *= sq[i];
    }

    float carry = stLI[b];
    float x = g_r[lane * BATCH + b];

    #pragma unroll 1
    for (int t0 = 0; t0 < T_STEPS; t0 += 32) {
        const int tn = t0 + 32 + lane;
        const float xn = (tn < T_STEPS) ? g_r[tn * BATCH + b] : 0.f;

        float y = x, up;
        up = __shfl_up_sync(0xffffffffu, y, 1);  if (lane >= 1)  y = fmaf(l1,  up, y);
        up = __shfl_up_sync(0xffffffffu, y, 2);  if (lane >= 2)  y = fmaf(l2,  up, y);
        up = __shfl_up_sync(0xffffffffu, y, 4);  if (lane >= 4)  y = fmaf(l4,  up, y);
        up = __shfl_up_sync(0xffffffffu, y, 8);  if (lane >= 8)  y = fmaf(l8,  up, y);
        up = __shfl_up_sync(0xffffffffu, y, 16); if (lane >= 16) y = fmaf(l16, up, y);

        const float li = fmaf(lpow, carry, y);
        if (t0 + lane < T_STEPS)
            out[DEC_OFF + (size_t)(t0 + lane) * BATCH + b] = li;
        carry = __shfl_sync(0xffffffffu, li, 31);
        x = xn;
    }
}

// ---------------------------------------------------------------------------
extern "C" void kernel_launch(void* const* d_in, const int* in_sizes, int n_in,
                              void* d_out, int out_size)
{
    const float* x    = (const float*)d_in[0];
    const float* st   = (const float*)d_in[1];
    const float* stLI = (const float*)d_in[2];
    const float* W1   = (const float*)d_in[3];
    const float* W2   = (const float*)d_in[4];
    const float* a_   = (const float*)d_in[5];
    const float* b_   = (const float*)d_in[6];
    const float* c_   = (const float*)d_in[7];
    const float* d_   = (const float*)d_in[8];
    const float* v2_  = (const float*)d_in[9];
    const float* v1_  = (const float*)d_in[10];
    const float* v0_  = (const float*)d_in[11];
    const float* tau_ = (const float*)d_in[12];
    const float* th_  = (const float*)d_in[13];
    const float* lk_  = (const float*)d_in[14];
    const float* ts_  = (const float*)d_in[15];
    float* out = (float*)d_out;

    const int smem_bytes = 2 * STAGEW * (int)sizeof(uint32_t);   // 73728
    cudaFuncSetAttribute(gemm_f16pair_kernel,
                         cudaFuncAttributeMaxDynamicSharedMemorySize, smem_bytes);

    dim3 ggrid(MROWS / 128, NDIM / 128);   // (500, 4)
    gemm_f16pair_kernel<<<ggrid, 512, smem_bytes>>>(x, W1);
    scan_kernel<<<(BATCH * NDIM) / 128, 128>>>(st, a_, b_, c_, d_, v2_, v1_,
                                               v0_, tau_, th_, ts_, out);
    readout_reduce_kernel<<<T_STEPS * BATCH, 128>>>(out, W2);
    li_kernel<<<BATCH, 32>>>(stLI, lk_, out);
}